// round 2
// baseline (speedup 1.0000x reference)
#include <cuda_runtime.h>

// Problem constants
#define NPTS   16384
#define NCHAN  64
#define DX     100
#define DY     88
#define DZ     80
#define PLANE  (DX*DY*DZ)          // 704000 elements per channel

#define WPB    8                   // warps per block
#define GRID   1184                // 148 SMs * 8 resident CTAs -> exactly one wave
#define TOTALW (GRID*WPB)          // 9472 warps; each handles 1-2 points

// Deterministic reduction scratch + completion counter (no heap allocs).
__device__ float        g_partials[GRID];
__device__ unsigned int g_count = 0;

__device__ __forceinline__ int redirect(int v, int idx0, int m) {
    int r = (v - idx0) % m;
    return (r < 0) ? r + m : r;
}

__device__ __forceinline__ int voxel_index(const int* __restrict__ pts, int b) {
    const int x = redirect(pts[b*3+0],  25, DX);
    const int y = redirect(pts[b*3+1], 225, DY);
    const int z = redirect(pts[b*3+2],  28, DZ);
    return x*(DY*DZ) + y*DZ + z;
}

// Per-point loss: lane handles channels lane and lane+32 (6 independent LDGs),
// returns the point's (loss_pos + loss_neg) on lane 0.
__device__ __forceinline__ float point_loss(const float* __restrict__ pf,
                                            const float* __restrict__ pq,
                                            const float* __restrict__ pn,
                                            int lane)
{
    float dpos = 0.0f, dneg = 0.0f;
#pragma unroll
    for (int i = 0; i < 2; i++) {
        const int c = lane + i*32;
        const float f = __ldg(pf + c*PLANE);
        const float p = __ldg(pq + c*PLANE);
        const float n = __ldg(pn + c*PLANE);
        const float dp = f - p;
        const float dn = f - n;
        dpos = fmaf(dp, dp, dpos);
        dneg = fmaf(dn, dn, dneg);
    }
#pragma unroll
    for (int off = 16; off > 0; off >>= 1) {
        dpos += __shfl_xor_sync(0xffffffffu, dpos, off);
        dneg += __shfl_xor_sync(0xffffffffu, dneg, off);
    }
    const float loss_pos = dpos * dpos;
    float t = fmaxf(1.0f - sqrtf(dneg), 0.0f);   // MARGIN = 1.0
    return loss_pos + t * t;
}

__global__ void __launch_bounds__(256, 8)
ccl_fused_kernel(const float* __restrict__ fixf,
                 const float* __restrict__ movf,
                 const int*   __restrict__ fp,
                 const int*   __restrict__ pp,
                 const int*   __restrict__ np_,
                 float*       __restrict__ out)
{
    const int warp = threadIdx.x >> 5;
    const int lane = threadIdx.x & 31;
    const int w    = blockIdx.x * WPB + warp;       // global warp id

    // Warp w handles point w and (if it exists) point w + TOTALW.
    const int b0 = w;
    const int b1 = w + TOTALW;
    const bool has1 = (b1 < NPTS);

    // ---- point 0 address setup ----
    const int f0 = voxel_index(fp,  b0);
    const int p0 = voxel_index(pp,  b0);
    const int n0 = voxel_index(np_, b0);

    // ---- point 1 address setup (predicated) ----
    int f1 = 0, p1 = 0, n1 = 0;
    if (has1) {
        f1 = voxel_index(fp,  b1);
        p1 = voxel_index(pp,  b1);
        n1 = voxel_index(np_, b1);
    }

    // ---- issue all loads for both points concurrently (up to 12 LDGs/lane) ----
    float dpos0 = 0.f, dneg0 = 0.f, dpos1 = 0.f, dneg1 = 0.f;
    float va[6], vb[6];
#pragma unroll
    for (int i = 0; i < 2; i++) {
        const int c = lane + i*32;
        va[i*3+0] = __ldg(fixf + f0 + c*PLANE);
        va[i*3+1] = __ldg(movf + p0 + c*PLANE);
        va[i*3+2] = __ldg(movf + n0 + c*PLANE);
        if (has1) {
            vb[i*3+0] = __ldg(fixf + f1 + c*PLANE);
            vb[i*3+1] = __ldg(movf + p1 + c*PLANE);
            vb[i*3+2] = __ldg(movf + n1 + c*PLANE);
        }
    }
#pragma unroll
    for (int i = 0; i < 2; i++) {
        float dp = va[i*3+0] - va[i*3+1];
        float dn = va[i*3+0] - va[i*3+2];
        dpos0 = fmaf(dp, dp, dpos0);
        dneg0 = fmaf(dn, dn, dneg0);
        if (has1) {
            float dp1 = vb[i*3+0] - vb[i*3+1];
            float dn1 = vb[i*3+0] - vb[i*3+2];
            dpos1 = fmaf(dp1, dp1, dpos1);
            dneg1 = fmaf(dn1, dn1, dneg1);
        }
    }

    // ---- warp reductions ----
#pragma unroll
    for (int off = 16; off > 0; off >>= 1) {
        dpos0 += __shfl_xor_sync(0xffffffffu, dpos0, off);
        dneg0 += __shfl_xor_sync(0xffffffffu, dneg0, off);
        dpos1 += __shfl_xor_sync(0xffffffffu, dpos1, off);
        dneg1 += __shfl_xor_sync(0xffffffffu, dneg1, off);
    }

    __shared__ float s_loss[WPB];
    if (lane == 0) {
        float lp0 = dpos0 * dpos0;
        float t0  = fmaxf(1.0f - sqrtf(dneg0), 0.0f);
        float acc = lp0 + t0 * t0;
        if (has1) {
            float lp1 = dpos1 * dpos1;
            float t1  = fmaxf(1.0f - sqrtf(dneg1), 0.0f);
            acc += lp1 + t1 * t1;
        }
        s_loss[warp] = acc;
    }
    __syncthreads();

    // ---- block partial + last-block final reduce (deterministic order) ----
    __shared__ bool s_last;
    if (threadIdx.x == 0) {
        float acc = 0.0f;
#pragma unroll
        for (int i = 0; i < WPB; i++) acc += s_loss[i];
        g_partials[blockIdx.x] = acc;
        __threadfence();
        unsigned int prev = atomicAdd(&g_count, 1u);
        s_last = (prev == GRID - 1);
    }
    __syncthreads();

    if (s_last) {
        __shared__ float s_red[256];
        float v = 0.0f;
        // fixed strided order: deterministic
        for (int i = threadIdx.x; i < GRID; i += 256)
            v += g_partials[i];
        s_red[threadIdx.x] = v;
        __syncthreads();
#pragma unroll
        for (int off = 128; off > 0; off >>= 1) {
            if (threadIdx.x < off) s_red[threadIdx.x] += s_red[threadIdx.x + off];
            __syncthreads();
        }
        if (threadIdx.x == 0) {
            // loss = sum / (2 * 2B) * 1e6
            out[0] = s_red[0] * (1000000.0f / (4.0f * (float)NPTS));
            g_count = 0;   // reset for next (graph-replayed) launch
        }
    }
}

extern "C" void kernel_launch(void* const* d_in, const int* in_sizes, int n_in,
                              void* d_out, int out_size)
{
    const float* fixf = (const float*)d_in[0];
    const float* movf = (const float*)d_in[1];
    const int*   fp   = (const int*)d_in[2];
    const int*   pp   = (const int*)d_in[3];
    const int*   np_  = (const int*)d_in[4];
    float* out = (float*)d_out;

    ccl_fused_kernel<<<GRID, 256>>>(fixf, movf, fp, pp, np_, out);
}

// round 3
// speedup vs baseline: 1.3846x; 1.3846x over previous
#include <cuda_runtime.h>

// Problem constants
#define NPTS   16384
#define NCHAN  64
#define DX     100
#define DY     88
#define DZ     80
#define PLANE  (DX*DY*DZ)          // 704000 floats per channel plane

// 2 threads per point -> 32768 threads = 128 blocks * 256 (single wave, all resident)
#define TPB    256
#define GRID   (NPTS * 2 / TPB)    // 128

__device__ float        g_partials[GRID];
__device__ unsigned int g_count = 0;

__device__ __forceinline__ int redirect(int v, int idx0, int m) {
    int r = (v - idx0) % m;
    return (r < 0) ? r + m : r;
}

__device__ __forceinline__ int voxel_index(const int* __restrict__ pts, int b) {
    const int x = redirect(pts[b*3+0],  25, DX);
    const int y = redirect(pts[b*3+1], 225, DY);
    const int z = redirect(pts[b*3+2],  28, DZ);
    return x*(DY*DZ) + y*DZ + z;
}

__global__ void __launch_bounds__(TPB, 1)
ccl_kernel(const float* __restrict__ fixf,
           const float* __restrict__ movf,
           const int*   __restrict__ fp,
           const int*   __restrict__ pp,
           const int*   __restrict__ np_,
           float*       __restrict__ out)
{
    const int tid  = blockIdx.x * TPB + threadIdx.x;
    const int b    = tid >> 1;          // point id
    const int half = tid & 1;           // channel half: 0 -> [0,32), 1 -> [32,64)

    const int fv = voxel_index(fp,  b);
    const int pv = voxel_index(pp,  b);
    const int nv = voxel_index(np_, b);

    const float* __restrict__ pf = fixf + fv + half * 32 * PLANE;
    const float* __restrict__ pq = movf + pv + half * 32 * PLANE;
    const float* __restrict__ pn = movf + nv + half * 32 * PLANE;

    // Walk 32 channels in (chip-wide, naturally lockstep) order.
    // Unroll 8 -> 24 independent loads in flight per thread.
    float dpos = 0.0f, dneg = 0.0f;
#pragma unroll 8
    for (int c = 0; c < 32; c++) {
        const float f = __ldg(pf + c * PLANE);
        const float p = __ldg(pq + c * PLANE);
        const float n = __ldg(pn + c * PLANE);
        const float dp = f - p;
        const float dn = f - n;
        dpos = fmaf(dp, dp, dpos);
        dneg = fmaf(dn, dn, dneg);
    }

    // Combine the two channel-halves of this point (adjacent lanes).
    dpos += __shfl_xor_sync(0xffffffffu, dpos, 1);
    dneg += __shfl_xor_sync(0xffffffffu, dneg, 1);

    // Per-point loss on the even lane; odd lane contributes 0.
    float loss = 0.0f;
    if (half == 0) {
        const float lp = dpos * dpos;
        float t = fmaxf(1.0f - sqrtf(dneg), 0.0f);   // MARGIN = 1.0
        loss = lp + t * t;
    }

    // Warp reduce the losses (16 points per warp).
#pragma unroll
    for (int off = 16; off > 0; off >>= 1)
        loss += __shfl_xor_sync(0xffffffffu, loss, off);

    __shared__ float s_loss[TPB / 32];
    const int warp = threadIdx.x >> 5;
    const int lane = threadIdx.x & 31;
    if (lane == 0) s_loss[warp] = loss;
    __syncthreads();

    __shared__ bool s_last;
    if (threadIdx.x == 0) {
        float acc = 0.0f;
#pragma unroll
        for (int i = 0; i < TPB / 32; i++) acc += s_loss[i];
        g_partials[blockIdx.x] = acc;
        __threadfence();
        unsigned int prev = atomicAdd(&g_count, 1u);
        s_last = (prev == GRID - 1);
    }
    __syncthreads();

    if (s_last) {
        // Final deterministic reduction over GRID=128 partials.
        __shared__ float s_red[128];
        if (threadIdx.x < 128) s_red[threadIdx.x] = g_partials[threadIdx.x];
        __syncthreads();
#pragma unroll
        for (int off = 64; off > 0; off >>= 1) {
            if (threadIdx.x < off) s_red[threadIdx.x] += s_red[threadIdx.x + off];
            __syncthreads();
        }
        if (threadIdx.x == 0) {
            // loss = sum / (2 * 2B) * 1e6
            out[0] = s_red[0] * (1000000.0f / (4.0f * (float)NPTS));
            g_count = 0;   // reset for graph replay
        }
    }
}

extern "C" void kernel_launch(void* const* d_in, const int* in_sizes, int n_in,
                              void* d_out, int out_size)
{
    const float* fixf = (const float*)d_in[0];
    const float* movf = (const float*)d_in[1];
    const int*   fp   = (const int*)d_in[2];
    const int*   pp   = (const int*)d_in[3];
    const int*   np_  = (const int*)d_in[4];
    float* out = (float*)d_out;

    ccl_kernel<<<GRID, TPB>>>(fixf, movf, fp, pp, np_, out);
}